// round 7
// baseline (speedup 1.0000x reference)
#include <cuda_runtime.h>

// DFMB PS ROI Align for GB300.
// Shapes: C=10, PH=PW=7 (P=49), H=W=34, S=4 subsamples/dim, N=16384 rois.
//
// Strategy:
//  1) transpose feature map to [p][y][x][c] (c padded to 16) so channels are
//     contiguous -> gathers become 40B contiguous bursts (1 line / position).
//  2) Exploit separability of the 4x4 subsample bilinear sum:
//       sum over samples = Sum_y Wy(y) Sum_x Wx(x) v(y,x)
//     over a 4x4 integer window per bin (footprint bound proven from
//     bin_w <= 12.5/7). count = (sum keepY)*(sum keepX).
//  3) Two-phase block: phase1 one thread/bin builds Wx[4],Wy[4] in smem
//     (geometry computed once per bin); phase2 16-lane groups (lane=channel)
//     do the weighted window gather with zero-weight rows/cols skipped.

#define NC   10
#define CP   16        // padded channel stride (power of 2, 64B/position)
#define NPH  7
#define NPW  7
#define NP   49
#define NH   34
#define NW   34
#define NHW  1156
#define ROWSTRIDE (NW * CP)   // 544

__device__ float g_ft_t[NP * NHW * CP];   // 49*1156*16 floats = 3.63 MB scratch

// ---------------------------------------------------------------------------
// Kernel 1: transpose [C][P][H*W] -> [P][H*W][CP] with zero padding c>=10
// ---------------------------------------------------------------------------
__global__ __launch_bounds__(256) void transpose_kernel(const float* __restrict__ ft) {
    int idx = blockIdx.x * 256 + threadIdx.x;
    const int total = NP * NHW * CP;
    if (idx >= total) return;
    int c    = idx & (CP - 1);
    int rest = idx >> 4;            // p*NHW + yx
    int yx   = rest % NHW;
    int p    = rest / NHW;
    float v = 0.0f;
    if (c < NC) v = ft[(c * NP + p) * NHW + yx];
    g_ft_t[idx] = v;
}

// ---------------------------------------------------------------------------
// Kernel 2: main ROI align
// ---------------------------------------------------------------------------
struct BinInfo {
    float wx[4];
    float wy[4];
    float invc;     // 1 / max(count, 1)
    int   base;     // element offset into g_ft_t of window origin (lane 0)
    int   outbase;  // n*490 + p, or -1 for out-of-range bins
};

__global__ __launch_bounds__(256) void roi_kernel(const float* __restrict__ rois,
                                                  float* __restrict__ out,
                                                  int nbins) {
    __shared__ BinInfo sb[256];
    const int tid = threadIdx.x;
    const int bin = blockIdx.x * 256 + tid;

    // ---------------- Phase 1: per-bin geometry -> smem -------------------
    {
        BinInfo bi;
        #pragma unroll
        for (int s = 0; s < 4; s++) { bi.wx[s] = 0.0f; bi.wy[s] = 0.0f; }
        bi.invc = 1.0f; bi.base = 0; bi.outbase = -1;

        if (bin < nbins) {
            int n  = bin / NP;
            int p  = bin - n * NP;
            int ph = p / NPW;
            int pw = p - ph * NPW;

            const float* r = rois + n * 5;
            float rsw = r[1] * 0.0625f;   // /16 exact
            float rsh = r[2] * 0.0625f;
            float rew = r[3] * 0.0625f;
            float reh = r[4] * 0.0625f;

            float roi_h = reh - rsh; roi_h = (roi_h > 0.1f) ? roi_h : 0.1f;
            float roi_w = rew - rsw; roi_w = (roi_w > 0.1f) ? roi_w : 0.1f;
            float bin_h = roi_h / 7.0f;          // IEEE div, matches reference
            float bin_w = roi_w / 7.0f;
            float sub_h = bin_h * 0.25f;         // /4 exact
            float sub_w = bin_w * 0.25f;

            // no FMA contraction: floor() boundary must match reference
            float hstart = floorf(__fadd_rn(rsh, __fmul_rn((float)ph, bin_h)));
            float wstart = floorf(__fadd_rn(rsw, __fmul_rn((float)pw, bin_w)));

            // ---- X direction ----
            float ckx = 0.0f;
            int ax = 0;
            #pragma unroll
            for (int j = 0; j < 4; j++) {
                float w   = __fadd_rn(wstart, __fmul_rn((float)j + 0.5f, sub_w));
                float x1f = floorf(w);
                float x2f = ceilf(w);
                int x1 = (int)x1f; x1 = max(0, min(NW - 1, x1));
                int x2 = (int)x2f; x2 = max(0, min(NW - 1, x2));
                if (j == 0) ax = x1;   // window origin; all corners in [ax, ax+3]
                float kx  = (w > -1.0f && w < (float)NW) ? 1.0f : 0.0f;
                float x1v = (x1f >= 0.0f && x1f < (float)NW) ? kx : 0.0f;
                float x2v = (x2f >= 0.0f && x2f < (float)NW) ? kx : 0.0f;
                float dx  = w - (float)x1;       // vs CLAMPED corner (ref semantics)
                float wa  = x1v * (1.0f - dx);
                float wb  = x2v * dx;
                int s1 = x1 - ax, s2 = x2 - ax;
                #pragma unroll
                for (int s = 0; s < 4; s++)
                    bi.wx[s] += (s1 == s ? wa : 0.0f) + (s2 == s ? wb : 0.0f);
                ckx += kx;
            }

            // ---- Y direction ----
            float cky = 0.0f;
            int by = 0;
            #pragma unroll
            for (int j = 0; j < 4; j++) {
                float h   = __fadd_rn(hstart, __fmul_rn((float)j + 0.5f, sub_h));
                float y1f = floorf(h);
                float y2f = ceilf(h);
                int y1 = (int)y1f; y1 = max(0, min(NH - 1, y1));
                int y2 = (int)y2f; y2 = max(0, min(NH - 1, y2));
                if (j == 0) by = y1;
                float ky  = (h > -1.0f && h < (float)NH) ? 1.0f : 0.0f;
                float y1v = (y1f >= 0.0f && y1f < (float)NH) ? ky : 0.0f;
                float y2v = (y2f >= 0.0f && y2f < (float)NH) ? ky : 0.0f;
                float dy  = h - (float)y1;
                float wa  = y1v * (1.0f - dy);
                float wb  = y2v * dy;
                int s1 = y1 - by, s2 = y2 - by;
                #pragma unroll
                for (int s = 0; s < 4; s++)
                    bi.wy[s] += (s1 == s ? wa : 0.0f) + (s2 == s ? wb : 0.0f);
                cky += ky;
            }

            float count = ckx * cky;
            float denom = (count > 0.0f) ? count : 1.0f;
            bi.invc    = 1.0f / denom;
            bi.base    = (p * NHW + by * NW + ax) * CP;
            bi.outbase = n * (NC * NP) + p;
        }
        sb[tid] = bi;
    }
    __syncthreads();

    // ---------------- Phase 2: channel-parallel gather --------------------
    const int lane = tid & 15;          // lane = channel (0..9 active)
    const int g0   = tid & ~15;         // group's first bin slot in smem

    #pragma unroll 1
    for (int i = 0; i < 16; i++) {
        const BinInfo& b = sb[g0 + i];
        if (lane < NC) {
            float acc = 0.0f;
            const float* src = g_ft_t + b.base + lane;
            #pragma unroll
            for (int r = 0; r < 4; r++) {
                float wyr = b.wy[r];
                if (wyr != 0.0f) {
                    const float* rowp = src + r * ROWSTRIDE;
                    #pragma unroll
                    for (int s = 0; s < 4; s++) {
                        float wxs = b.wx[s];
                        if (wxs != 0.0f) {
                            acc += (wyr * wxs) * rowp[s * CP];
                        }
                    }
                }
            }
            if (b.outbase >= 0) {
                out[b.outbase + lane * NP] = acc * b.invc;
            }
        }
    }
}

// ---------------------------------------------------------------------------
extern "C" void kernel_launch(void* const* d_in, const int* in_sizes, int n_in,
                              void* d_out, int out_size) {
    const float* ft   = (const float*)d_in[0];   // (1, 490, 34, 34)
    const float* rois = (const float*)d_in[1];   // (N, 5)
    float* out = (float*)d_out;                  // (N, 10, 49)

    int N = in_sizes[1] / 5;
    int nbins = N * NP;

    {
        const int total = NP * NHW * CP;
        int blocks = (total + 255) / 256;
        transpose_kernel<<<blocks, 256>>>(ft);
    }
    {
        int blocks = (nbins + 255) / 256;
        roi_kernel<<<blocks, 256>>>(rois, out, nbins);
    }
}

// round 8
// speedup vs baseline: 1.5197x; 1.5197x over previous
#include <cuda_runtime.h>

// DFMB PS ROI Align for GB300. C=10, PH=PW=7 (P=49), H=W=34, S=4, N=16384.
//
// R7 strategy:
//  - transpose feature map to [p][y][x][c_pad16]  (64B per position, aligned)
//  - separable 4x4 subsample bilinear -> per-bin 4x4 window weights
//  - phase 1 (1 thread/bin): geometry ONCE, emit compact list of
//    (weight*invc, element offset) for nonzero-weight positions (avg ~9/16)
//  - phase 2 (4 lanes/bin, lane = channel quad): branch-free loop:
//    LDS.64 entry + LDG.128 float4 + 4 FFMA. 8 consecutive bins per warp
//    -> uniform trip counts (same ROI) and coalesced 32B store runs.

#define NC   10
#define CP   16        // padded channel stride (64B per position)
#define NPH  7
#define NPW  7
#define NP   49
#define NH   34
#define NW   34
#define NHW  1156
#define ROWSTRIDE (NW * CP)   // 544 floats

__device__ float g_ft_t[NP * NHW * CP];   // 3.63 MB scratch

// ---------------------------------------------------------------------------
// Kernel 1: transpose [C][P][H*W] -> [P][H*W][CP], zero pad c>=10
// ---------------------------------------------------------------------------
__global__ __launch_bounds__(256) void transpose_kernel(const float* __restrict__ ft) {
    int idx = blockIdx.x * 256 + threadIdx.x;
    const int total = NP * NHW * CP;
    if (idx >= total) return;
    int c    = idx & (CP - 1);
    int rest = idx >> 4;
    int yx   = rest % NHW;
    int p    = rest / NHW;
    float v = 0.0f;
    if (c < NC) v = ft[(c * NP + p) * NHW + yx];
    g_ft_t[idx] = v;
}

// ---------------------------------------------------------------------------
// Kernel 2: main ROI align
// ---------------------------------------------------------------------------
struct __align__(16) BinList {
    float2 e[16];        // .x = weight*invc, .y = int offset (bit-cast)
    int n;               // number of active entries
    int outb;            // n*490 + p, or -1
    int pad0, pad1;
};                        // 144 B

__global__ __launch_bounds__(256) void roi_kernel(const float* __restrict__ rois,
                                                  float* __restrict__ out,
                                                  int nbins) {
    __shared__ BinList sb[256];          // 36864 B (< 48KB static limit)
    const int tid = threadIdx.x;
    const int bin = blockIdx.x * 256 + tid;

    // ---------------- Phase 1: per-bin geometry -> compact list -----------
    {
        int nent = 0;
        int outb = -1;

        if (bin < nbins) {
            int n  = bin / NP;
            int p  = bin - n * NP;
            int ph = p / NPW;
            int pw = p - ph * NPW;

            const float* r = rois + n * 5;
            float rsw = r[1] * 0.0625f;
            float rsh = r[2] * 0.0625f;
            float rew = r[3] * 0.0625f;
            float reh = r[4] * 0.0625f;

            float roi_h = reh - rsh; roi_h = (roi_h > 0.1f) ? roi_h : 0.1f;
            float roi_w = rew - rsw; roi_w = (roi_w > 0.1f) ? roi_w : 0.1f;
            float bin_h = roi_h / 7.0f;
            float bin_w = roi_w / 7.0f;
            float sub_h = bin_h * 0.25f;
            float sub_w = bin_w * 0.25f;

            // no FMA contraction: floor() boundary must match reference
            float hstart = floorf(__fadd_rn(rsh, __fmul_rn((float)ph, bin_h)));
            float wstart = floorf(__fadd_rn(rsw, __fmul_rn((float)pw, bin_w)));

            float wx0 = 0.f, wx1 = 0.f, wx2 = 0.f, wx3 = 0.f;
            float wy0 = 0.f, wy1 = 0.f, wy2 = 0.f, wy3 = 0.f;

            // ---- X direction ----
            float ckx = 0.0f;
            int ax = 0;
            #pragma unroll
            for (int j = 0; j < 4; j++) {
                float w   = __fadd_rn(wstart, __fmul_rn((float)j + 0.5f, sub_w));
                float x1f = floorf(w);
                float x2f = ceilf(w);
                int x1 = (int)x1f; x1 = max(0, min(NW - 1, x1));
                int x2 = (int)x2f; x2 = max(0, min(NW - 1, x2));
                if (j == 0) ax = x1;   // window origin; corners land in [ax, ax+3]
                float kx  = (w > -1.0f && w < (float)NW) ? 1.0f : 0.0f;
                float x1v = (x1f >= 0.0f && x1f < (float)NW) ? kx : 0.0f;
                float x2v = (x2f >= 0.0f && x2f < (float)NW) ? kx : 0.0f;
                float dx  = w - (float)x1;       // vs CLAMPED corner (ref semantics)
                float wa  = x1v * (1.0f - dx);
                float wb  = x2v * dx;
                int s1 = x1 - ax, s2 = x2 - ax;
                wx0 += (s1 == 0 ? wa : 0.f) + (s2 == 0 ? wb : 0.f);
                wx1 += (s1 == 1 ? wa : 0.f) + (s2 == 1 ? wb : 0.f);
                wx2 += (s1 == 2 ? wa : 0.f) + (s2 == 2 ? wb : 0.f);
                wx3 += (s1 == 3 ? wa : 0.f) + (s2 == 3 ? wb : 0.f);
                ckx += kx;
            }

            // ---- Y direction ----
            float cky = 0.0f;
            int by = 0;
            #pragma unroll
            for (int j = 0; j < 4; j++) {
                float h   = __fadd_rn(hstart, __fmul_rn((float)j + 0.5f, sub_h));
                float y1f = floorf(h);
                float y2f = ceilf(h);
                int y1 = (int)y1f; y1 = max(0, min(NH - 1, y1));
                int y2 = (int)y2f; y2 = max(0, min(NH - 1, y2));
                if (j == 0) by = y1;
                float ky  = (h > -1.0f && h < (float)NH) ? 1.0f : 0.0f;
                float y1v = (y1f >= 0.0f && y1f < (float)NH) ? ky : 0.0f;
                float y2v = (y2f >= 0.0f && y2f < (float)NH) ? ky : 0.0f;
                float dy  = h - (float)y1;
                float wa  = y1v * (1.0f - dy);
                float wb  = y2v * dy;
                int s1 = y1 - by, s2 = y2 - by;
                wy0 += (s1 == 0 ? wa : 0.f) + (s2 == 0 ? wb : 0.f);
                wy1 += (s1 == 1 ? wa : 0.f) + (s2 == 1 ? wb : 0.f);
                wy2 += (s1 == 2 ? wa : 0.f) + (s2 == 2 ? wb : 0.f);
                wy3 += (s1 == 3 ? wa : 0.f) + (s2 == 3 ? wb : 0.f);
                cky += ky;
            }

            float count = ckx * cky;
            float denom = (count > 0.0f) ? count : 1.0f;
            float invc  = 1.0f / denom;
            int   boff  = (p * NHW + by * NW + ax) * CP;
            outb        = n * (NC * NP) + p;

            float wxs[4] = {wx0, wx1, wx2, wx3};
            float wys[4] = {wy0 * invc, wy1 * invc, wy2 * invc, wy3 * invc};

            #pragma unroll
            for (int rr = 0; rr < 4; rr++) {
                #pragma unroll
                for (int ss = 0; ss < 4; ss++) {
                    float wv = wys[rr] * wxs[ss];
                    if (wv != 0.0f) {
                        sb[tid].e[nent] = make_float2(
                            wv, __int_as_float(boff + rr * ROWSTRIDE + ss * CP));
                        nent++;
                    }
                }
            }
        }
        sb[tid].n = nent;
        sb[tid].outb = outb;
    }
    __syncthreads();

    // ---------------- Phase 2: channel-quad parallel gather ---------------
    const int subc = tid & 3;           // channel quad: floats [4*subc, 4*subc+4)
    const int g    = tid >> 2;          // 0..63

    #pragma unroll 1
    for (int i = 0; i < 4; i++) {
        const BinList& b = sb[i * 64 + g];   // warp covers 8 CONSECUTIVE bins
        const int n = b.n;
        const float* src = g_ft_t + 4 * subc;
        float ax = 0.f, ay = 0.f, az = 0.f, aw = 0.f;

        #pragma unroll 1
        for (int k = 0; k < n; k++) {
            float2 e = b.e[k];                 // LDS.64 (broadcast in quad)
            float  w = e.x;
            int  off = __float_as_int(e.y);
            float4 v = *(const float4*)(src + off);   // LDG.128, 16B aligned
            ax = fmaf(w, v.x, ax);
            ay = fmaf(w, v.y, ay);
            az = fmaf(w, v.z, az);
            aw = fmaf(w, v.w, aw);
        }

        const int ob = b.outb;
        if (ob >= 0 && subc < 3) {
            float* o = out + ob + subc * 4 * NP;
            o[0]  = ax;                        // c = 4*subc
            o[NP] = ay;                        // c = 4*subc+1
            if (subc < 2) {
                o[2 * NP] = az;                // c = 4*subc+2
                o[3 * NP] = aw;                // c = 4*subc+3
            }
        }
    }
}

// ---------------------------------------------------------------------------
extern "C" void kernel_launch(void* const* d_in, const int* in_sizes, int n_in,
                              void* d_out, int out_size) {
    const float* ft   = (const float*)d_in[0];   // (1, 490, 34, 34)
    const float* rois = (const float*)d_in[1];   // (N, 5)
    float* out = (float*)d_out;                  // (N, 10, 49)

    int N = in_sizes[1] / 5;
    int nbins = N * NP;

    {
        const int total = NP * NHW * CP;
        transpose_kernel<<<(total + 255) / 256, 256>>>(ft);
    }
    {
        roi_kernel<<<(nbins + 255) / 256, 256>>>(rois, out, nbins);
    }
}

// round 9
// speedup vs baseline: 1.5321x; 1.0082x over previous
#include <cuda_runtime.h>

// DFMB PS ROI Align for GB300. C=10, PH=PW=7 (P=49), H=W=34, S=4, N=16384.
//
// R7 strategy:
//  - transpose feature map to [p][y][x][c_pad16]  (64B per position, aligned)
//  - separable 4x4 subsample bilinear -> per-bin 4x4 window weights
//  - phase 1 (1 thread/bin): geometry ONCE, emit compact list of
//    (weight*invc, element offset) for nonzero-weight positions (avg ~9/16)
//  - phase 2 (4 lanes/bin, lane = channel quad): branch-free loop:
//    LDS.64 entry + LDG.128 float4 + 4 FFMA. 8 consecutive bins per warp
//    -> uniform trip counts (same ROI) and coalesced 32B store runs.

#define NC   10
#define CP   16        // padded channel stride (64B per position)
#define NPH  7
#define NPW  7
#define NP   49
#define NH   34
#define NW   34
#define NHW  1156
#define ROWSTRIDE (NW * CP)   // 544 floats

__device__ float g_ft_t[NP * NHW * CP];   // 3.63 MB scratch

// ---------------------------------------------------------------------------
// Kernel 1: transpose [C][P][H*W] -> [P][H*W][CP], zero pad c>=10
// ---------------------------------------------------------------------------
__global__ __launch_bounds__(256) void transpose_kernel(const float* __restrict__ ft) {
    int idx = blockIdx.x * 256 + threadIdx.x;
    const int total = NP * NHW * CP;
    if (idx >= total) return;
    int c    = idx & (CP - 1);
    int rest = idx >> 4;
    int yx   = rest % NHW;
    int p    = rest / NHW;
    float v = 0.0f;
    if (c < NC) v = ft[(c * NP + p) * NHW + yx];
    g_ft_t[idx] = v;
}

// ---------------------------------------------------------------------------
// Kernel 2: main ROI align
// ---------------------------------------------------------------------------
struct __align__(16) BinList {
    float2 e[16];        // .x = weight*invc, .y = int offset (bit-cast)
    int n;               // number of active entries
    int outb;            // n*490 + p, or -1
    int pad0, pad1;
};                        // 144 B

__global__ __launch_bounds__(256) void roi_kernel(const float* __restrict__ rois,
                                                  float* __restrict__ out,
                                                  int nbins) {
    __shared__ BinList sb[256];          // 36864 B (< 48KB static limit)
    const int tid = threadIdx.x;
    const int bin = blockIdx.x * 256 + tid;

    // ---------------- Phase 1: per-bin geometry -> compact list -----------
    {
        int nent = 0;
        int outb = -1;

        if (bin < nbins) {
            int n  = bin / NP;
            int p  = bin - n * NP;
            int ph = p / NPW;
            int pw = p - ph * NPW;

            const float* r = rois + n * 5;
            float rsw = r[1] * 0.0625f;
            float rsh = r[2] * 0.0625f;
            float rew = r[3] * 0.0625f;
            float reh = r[4] * 0.0625f;

            float roi_h = reh - rsh; roi_h = (roi_h > 0.1f) ? roi_h : 0.1f;
            float roi_w = rew - rsw; roi_w = (roi_w > 0.1f) ? roi_w : 0.1f;
            float bin_h = roi_h / 7.0f;
            float bin_w = roi_w / 7.0f;
            float sub_h = bin_h * 0.25f;
            float sub_w = bin_w * 0.25f;

            // no FMA contraction: floor() boundary must match reference
            float hstart = floorf(__fadd_rn(rsh, __fmul_rn((float)ph, bin_h)));
            float wstart = floorf(__fadd_rn(rsw, __fmul_rn((float)pw, bin_w)));

            float wx0 = 0.f, wx1 = 0.f, wx2 = 0.f, wx3 = 0.f;
            float wy0 = 0.f, wy1 = 0.f, wy2 = 0.f, wy3 = 0.f;

            // ---- X direction ----
            float ckx = 0.0f;
            int ax = 0;
            #pragma unroll
            for (int j = 0; j < 4; j++) {
                float w   = __fadd_rn(wstart, __fmul_rn((float)j + 0.5f, sub_w));
                float x1f = floorf(w);
                float x2f = ceilf(w);
                int x1 = (int)x1f; x1 = max(0, min(NW - 1, x1));
                int x2 = (int)x2f; x2 = max(0, min(NW - 1, x2));
                if (j == 0) ax = x1;   // window origin; corners land in [ax, ax+3]
                float kx  = (w > -1.0f && w < (float)NW) ? 1.0f : 0.0f;
                float x1v = (x1f >= 0.0f && x1f < (float)NW) ? kx : 0.0f;
                float x2v = (x2f >= 0.0f && x2f < (float)NW) ? kx : 0.0f;
                float dx  = w - (float)x1;       // vs CLAMPED corner (ref semantics)
                float wa  = x1v * (1.0f - dx);
                float wb  = x2v * dx;
                int s1 = x1 - ax, s2 = x2 - ax;
                wx0 += (s1 == 0 ? wa : 0.f) + (s2 == 0 ? wb : 0.f);
                wx1 += (s1 == 1 ? wa : 0.f) + (s2 == 1 ? wb : 0.f);
                wx2 += (s1 == 2 ? wa : 0.f) + (s2 == 2 ? wb : 0.f);
                wx3 += (s1 == 3 ? wa : 0.f) + (s2 == 3 ? wb : 0.f);
                ckx += kx;
            }

            // ---- Y direction ----
            float cky = 0.0f;
            int by = 0;
            #pragma unroll
            for (int j = 0; j < 4; j++) {
                float h   = __fadd_rn(hstart, __fmul_rn((float)j + 0.5f, sub_h));
                float y1f = floorf(h);
                float y2f = ceilf(h);
                int y1 = (int)y1f; y1 = max(0, min(NH - 1, y1));
                int y2 = (int)y2f; y2 = max(0, min(NH - 1, y2));
                if (j == 0) by = y1;
                float ky  = (h > -1.0f && h < (float)NH) ? 1.0f : 0.0f;
                float y1v = (y1f >= 0.0f && y1f < (float)NH) ? ky : 0.0f;
                float y2v = (y2f >= 0.0f && y2f < (float)NH) ? ky : 0.0f;
                float dy  = h - (float)y1;
                float wa  = y1v * (1.0f - dy);
                float wb  = y2v * dy;
                int s1 = y1 - by, s2 = y2 - by;
                wy0 += (s1 == 0 ? wa : 0.f) + (s2 == 0 ? wb : 0.f);
                wy1 += (s1 == 1 ? wa : 0.f) + (s2 == 1 ? wb : 0.f);
                wy2 += (s1 == 2 ? wa : 0.f) + (s2 == 2 ? wb : 0.f);
                wy3 += (s1 == 3 ? wa : 0.f) + (s2 == 3 ? wb : 0.f);
                cky += ky;
            }

            float count = ckx * cky;
            float denom = (count > 0.0f) ? count : 1.0f;
            float invc  = 1.0f / denom;
            int   boff  = (p * NHW + by * NW + ax) * CP;
            outb        = n * (NC * NP) + p;

            float wxs[4] = {wx0, wx1, wx2, wx3};
            float wys[4] = {wy0 * invc, wy1 * invc, wy2 * invc, wy3 * invc};

            #pragma unroll
            for (int rr = 0; rr < 4; rr++) {
                #pragma unroll
                for (int ss = 0; ss < 4; ss++) {
                    float wv = wys[rr] * wxs[ss];
                    if (wv != 0.0f) {
                        sb[tid].e[nent] = make_float2(
                            wv, __int_as_float(boff + rr * ROWSTRIDE + ss * CP));
                        nent++;
                    }
                }
            }
        }
        sb[tid].n = nent;
        sb[tid].outb = outb;
    }
    __syncthreads();

    // ---------------- Phase 2: channel-quad parallel gather ---------------
    const int subc = tid & 3;           // channel quad: floats [4*subc, 4*subc+4)
    const int g    = tid >> 2;          // 0..63

    #pragma unroll 1
    for (int i = 0; i < 4; i++) {
        const BinList& b = sb[i * 64 + g];   // warp covers 8 CONSECUTIVE bins
        const int n = b.n;
        const float* src = g_ft_t + 4 * subc;
        float ax = 0.f, ay = 0.f, az = 0.f, aw = 0.f;

        #pragma unroll 1
        for (int k = 0; k < n; k++) {
            float2 e = b.e[k];                 // LDS.64 (broadcast in quad)
            float  w = e.x;
            int  off = __float_as_int(e.y);
            float4 v = *(const float4*)(src + off);   // LDG.128, 16B aligned
            ax = fmaf(w, v.x, ax);
            ay = fmaf(w, v.y, ay);
            az = fmaf(w, v.z, az);
            aw = fmaf(w, v.w, aw);
        }

        const int ob = b.outb;
        if (ob >= 0 && subc < 3) {
            float* o = out + ob + subc * 4 * NP;
            o[0]  = ax;                        // c = 4*subc
            o[NP] = ay;                        // c = 4*subc+1
            if (subc < 2) {
                o[2 * NP] = az;                // c = 4*subc+2
                o[3 * NP] = aw;                // c = 4*subc+3
            }
        }
    }
}

// ---------------------------------------------------------------------------
extern "C" void kernel_launch(void* const* d_in, const int* in_sizes, int n_in,
                              void* d_out, int out_size) {
    const float* ft   = (const float*)d_in[0];   // (1, 490, 34, 34)
    const float* rois = (const float*)d_in[1];   // (N, 5)
    float* out = (float*)d_out;                  // (N, 10, 49)

    int N = in_sizes[1] / 5;
    int nbins = N * NP;

    {
        const int total = NP * NHW * CP;
        transpose_kernel<<<(total + 255) / 256, 256>>>(ft);
    }
    {
        roi_kernel<<<(nbins + 255) / 256, 256>>>(rois, out, nbins);
    }
}